// round 3
// baseline (speedup 1.0000x reference)
#include <cuda_runtime.h>
#include <cuda_bf16.h>
#include <cstdint>

#define B_ROWS 16384
#define F_DIM  1024
#define C_COLS 1000
#define C_PAD  1024

// Scratch (static __device__ arrays allowed; no dynamic allocation)
__device__ __nv_bfloat16 g_Fb[(size_t)B_ROWS * F_DIM];   // normalized features, bf16
__device__ __nv_bfloat16 g_Pb[(size_t)C_PAD * F_DIM];    // normalized prototypes (padded), bf16
__device__ float g_rowsum[B_ROWS];

// ---------------------------------------------------------------------------
// Helpers (sm_80-era features only: cp.async, ldmatrix, mma.sync bf16 — the
// harness's ptxas target is plain sm_103, no 'a' features / tcgen05)
// ---------------------------------------------------------------------------
__device__ __forceinline__ uint32_t smem_u32(const void* p) {
    uint32_t a;
    asm("{ .reg .u64 t; cvta.to.shared.u64 t, %1; cvt.u32.u64 %0, t; }" : "=r"(a) : "l"(p));
    return a;
}
__device__ __forceinline__ void cp_async16(uint32_t dst, const void* src) {
    asm volatile("cp.async.cg.shared.global [%0], [%1], 16;" :: "r"(dst), "l"(src));
}
__device__ __forceinline__ void cp_commit() { asm volatile("cp.async.commit_group;" ::: "memory"); }

__device__ __forceinline__ void ldsm_x4(uint32_t& r0, uint32_t& r1, uint32_t& r2, uint32_t& r3,
                                        uint32_t addr) {
    asm volatile("ldmatrix.sync.aligned.m8n8.x4.shared.b16 {%0,%1,%2,%3}, [%4];"
                 : "=r"(r0), "=r"(r1), "=r"(r2), "=r"(r3) : "r"(addr));
}
__device__ __forceinline__ void mma_bf16(float* c, uint32_t a0, uint32_t a1, uint32_t a2,
                                         uint32_t a3, uint32_t b0, uint32_t b1) {
    asm volatile(
        "mma.sync.aligned.m16n8k16.row.col.f32.bf16.bf16.f32 "
        "{%0,%1,%2,%3}, {%4,%5,%6,%7}, {%8,%9}, {%0,%1,%2,%3};"
        : "+f"(c[0]), "+f"(c[1]), "+f"(c[2]), "+f"(c[3])
        : "r"(a0), "r"(a1), "r"(a2), "r"(a3), "r"(b0), "r"(b1));
}

// ---------------------------------------------------------------------------
// Kernels 1/2: L2-normalize rows -> bf16
// ---------------------------------------------------------------------------
__global__ void __launch_bounds__(256) norm_features_kernel(const float* __restrict__ in) {
    int row = blockIdx.x, tid = threadIdx.x;
    const float4* rin = (const float4*)(in + (size_t)row * F_DIM);
    float4 v = rin[tid];
    float ss = v.x * v.x + v.y * v.y + v.z * v.z + v.w * v.w;
#pragma unroll
    for (int o = 16; o; o >>= 1) ss += __shfl_xor_sync(0xffffffffu, ss, o);
    __shared__ float red[8];
    if ((tid & 31) == 0) red[tid >> 5] = ss;
    __syncthreads();
    if (tid < 8) {
        float t = red[tid];
#pragma unroll
        for (int o = 4; o; o >>= 1) t += __shfl_xor_sync(0x000000ffu, t, o);
        if (tid == 0) red[0] = t;
    }
    __syncthreads();
    float sc = 1.0f / fmaxf(sqrtf(red[0]), 1e-12f);
    __nv_bfloat162* dst = (__nv_bfloat162*)(g_Fb + (size_t)row * F_DIM);
    dst[tid * 2 + 0] = __floats2bfloat162_rn(v.x * sc, v.y * sc);
    dst[tid * 2 + 1] = __floats2bfloat162_rn(v.z * sc, v.w * sc);
    if (tid == 0) g_rowsum[row] = 0.0f;
}

__global__ void __launch_bounds__(256) norm_protos_kernel(const float* __restrict__ in) {
    int row = blockIdx.x, tid = threadIdx.x;
    __nv_bfloat162* dst = (__nv_bfloat162*)(g_Pb + (size_t)row * F_DIM);
    if (row >= C_COLS) {
        __nv_bfloat162 z = __floats2bfloat162_rn(0.f, 0.f);
        dst[tid * 2 + 0] = z;
        dst[tid * 2 + 1] = z;
        return;
    }
    const float4* rin = (const float4*)(in + (size_t)row * F_DIM);
    float4 v = rin[tid];
    float ss = v.x * v.x + v.y * v.y + v.z * v.z + v.w * v.w;
#pragma unroll
    for (int o = 16; o; o >>= 1) ss += __shfl_xor_sync(0xffffffffu, ss, o);
    __shared__ float red[8];
    if ((tid & 31) == 0) red[tid >> 5] = ss;
    __syncthreads();
    if (tid < 8) {
        float t = red[tid];
#pragma unroll
        for (int o = 4; o; o >>= 1) t += __shfl_xor_sync(0x000000ffu, t, o);
        if (tid == 0) red[0] = t;
    }
    __syncthreads();
    float sc = 1.0f / fmaxf(sqrtf(red[0]), 1e-12f);
    dst[tid * 2 + 0] = __floats2bfloat162_rn(v.x * sc, v.y * sc);
    dst[tid * 2 + 1] = __floats2bfloat162_rn(v.z * sc, v.w * sc);
}

// ---------------------------------------------------------------------------
// Kernel 3: bf16 mma.sync GEMM, CTA 128x128, BK=64, 4-stage cp.async pipeline
// 8 warps: wm = wid>>2 (0..1, 64 rows each), wn = wid&3 (0..3, 32 cols each)
// Epilogue: iso = |ds| * sqrt(max(1 - sim, 0)); direct store + row-sum atomics
// ---------------------------------------------------------------------------
#define STAGES 4
#define BK 64
#define KCHUNKS (F_DIM / BK)          // 16
#define PAD_BYTES 144                 // (64+8) bf16 per row
#define A_ST_BYTES (128 * PAD_BYTES)  // 18432
#define STAGE_BYTES (2 * A_ST_BYTES)  // 36864 (A then B)
#define GEMM_SMEM (STAGES * STAGE_BYTES)

__device__ __forceinline__ void load_tile(uint32_t base, int kc, int m0, int n0, int tid) {
    const char* fb = (const char*)g_Fb;
    const char* pb = (const char*)g_Pb;
    uint32_t st = base + (uint32_t)(kc % STAGES) * STAGE_BYTES;
#pragma unroll
    for (int it = 0; it < 4; it++) {
        int s = tid + it * 256;            // 0..1023
        int r = s >> 3, q = s & 7;
        cp_async16(st + (uint32_t)(r * PAD_BYTES + q * 16),
                   fb + (size_t)(m0 + r) * 2048 + (size_t)kc * 128 + q * 16);
    }
    uint32_t stB = st + A_ST_BYTES;
#pragma unroll
    for (int it = 0; it < 4; it++) {
        int s = tid + it * 256;
        int r = s >> 3, q = s & 7;
        cp_async16(stB + (uint32_t)(r * PAD_BYTES + q * 16),
                   pb + (size_t)(n0 + r) * 2048 + (size_t)kc * 128 + q * 16);
    }
    cp_commit();
}

__global__ void __launch_bounds__(256) gemm_kernel(const float* __restrict__ ds,
                                                   float* __restrict__ out) {
    extern __shared__ char smem_raw[];
    uint32_t base = smem_u32(smem_raw);

    int tid = threadIdx.x;
    int wid = tid >> 5, l = tid & 31;
    int wm = wid >> 2, wn = wid & 3;
    int m0 = blockIdx.y * 128, n0 = blockIdx.x * 128;

    float c[4][4][4];
#pragma unroll
    for (int i = 0; i < 4; i++)
#pragma unroll
        for (int j = 0; j < 4; j++)
#pragma unroll
            for (int k = 0; k < 4; k++) c[i][j][k] = 0.0f;

    // prologue
#pragma unroll
    for (int kc = 0; kc < STAGES - 1; kc++) load_tile(base, kc, m0, n0, tid);

    for (int kc = 0; kc < KCHUNKS; kc++) {
        if (kc + STAGES - 1 < KCHUNKS)
            asm volatile("cp.async.wait_group %0;" :: "n"(STAGES - 2) : "memory");
        else
            asm volatile("cp.async.wait_group 0;" ::: "memory");
        __syncthreads();

        int j = kc + STAGES - 1;
        if (j < KCHUNKS) load_tile(base, j, m0, n0, tid);

        uint32_t st = base + (uint32_t)(kc % STAGES) * STAGE_BYTES;
        uint32_t aBase = st + (uint32_t)(wm * 64) * PAD_BYTES;
        uint32_t bBase = st + A_ST_BYTES + (uint32_t)(wn * 32) * PAD_BYTES;

        int g = l >> 3;          // 0..3
        int r8 = l & 7;
#pragma unroll
        for (int ks = 0; ks < 4; ks++) {
            uint32_t a[4][4];
#pragma unroll
            for (int mt = 0; mt < 4; mt++) {
                // lanes: g0 rows 0-7 k0 | g1 rows 8-15 k0 | g2 rows 0-7 k8 | g3 rows 8-15 k8
                uint32_t addr = aBase + (uint32_t)((mt * 16 + (g & 1) * 8 + r8) * PAD_BYTES
                                                  + ks * 32 + (g >> 1) * 16);
                ldsm_x4(a[mt][0], a[mt][1], a[mt][2], a[mt][3], addr);
            }
            uint32_t b[4][2];
#pragma unroll
            for (int pair = 0; pair < 2; pair++) {
                // matrices: [ntile 2p, k-lo] [ntile 2p, k-hi] [ntile 2p+1, k-lo] [ntile 2p+1, k-hi]
                int ntile = pair * 2 + (g >> 1);
                uint32_t addr = bBase + (uint32_t)((ntile * 8 + r8) * PAD_BYTES
                                                  + ks * 32 + (g & 1) * 16);
                ldsm_x4(b[pair * 2][0], b[pair * 2][1], b[pair * 2 + 1][0], b[pair * 2 + 1][1], addr);
            }
#pragma unroll
            for (int mt = 0; mt < 4; mt++)
#pragma unroll
                for (int nt = 0; nt < 4; nt++)
                    mma_bf16(c[mt][nt], a[mt][0], a[mt][1], a[mt][2], a[mt][3],
                             b[nt][0], b[nt][1]);
        }
        __syncthreads();
    }

    // ---------------- epilogue ----------------
    float dsa = fabsf(ds[0]);
    float rs[4][2];
#pragma unroll
    for (int mt = 0; mt < 4; mt++) { rs[mt][0] = 0.0f; rs[mt][1] = 0.0f; }

#pragma unroll
    for (int mt = 0; mt < 4; mt++) {
        int mrow = m0 + wm * 64 + mt * 16 + (l >> 2);
#pragma unroll
        for (int nt = 0; nt < 4; nt++) {
            int col = n0 + wn * 32 + nt * 8 + 2 * (l & 3);
            float i0 = dsa * sqrtf(fmaxf(1.0f - c[mt][nt][0], 0.0f));
            float i1 = dsa * sqrtf(fmaxf(1.0f - c[mt][nt][1], 0.0f));
            float i2 = dsa * sqrtf(fmaxf(1.0f - c[mt][nt][2], 0.0f));
            float i3 = dsa * sqrtf(fmaxf(1.0f - c[mt][nt][3], 0.0f));
            if (col < C_COLS) {             // col even, C_COLS even -> col+1 valid too
                rs[mt][0] += i0 + i1;
                rs[mt][1] += i2 + i3;
                float2 v01 = make_float2(i0, i1);
                float2 v23 = make_float2(i2, i3);
                *(float2*)(out + (size_t)mrow * C_COLS + col) = v01;
                *(float2*)(out + (size_t)(mrow + 8) * C_COLS + col) = v23;
            }
        }
    }
    // reduce row sums over the 4 lanes sharing a row (xor 1, 2), then atomics
#pragma unroll
    for (int mt = 0; mt < 4; mt++) {
#pragma unroll
        for (int h = 0; h < 2; h++) {
            float v = rs[mt][h];
            v += __shfl_xor_sync(0xffffffffu, v, 1);
            v += __shfl_xor_sync(0xffffffffu, v, 2);
            if ((l & 3) == 0) {
                int mrow = m0 + wm * 64 + mt * 16 + (l >> 2) + h * 8;
                atomicAdd(&g_rowsum[mrow], v);
            }
        }
    }
}

// ---------------------------------------------------------------------------
// Kernel 4: logits = -(iso + rowmean) / temperature  (in-place on d_out)
// ---------------------------------------------------------------------------
__global__ void __launch_bounds__(256) finalize_kernel(float* __restrict__ out,
                                                       const float* __restrict__ temp) {
    int row = blockIdx.x;
    float m = g_rowsum[row] * (1.0f / (float)C_COLS);
    float invt = 1.0f / temp[0];
    for (int c = threadIdx.x; c < C_COLS; c += 256) {
        size_t i = (size_t)row * C_COLS + c;
        out[i] = -(out[i] + m) * invt;
    }
}

// ---------------------------------------------------------------------------
extern "C" void kernel_launch(void* const* d_in, const int* in_sizes, int n_in,
                              void* d_out, int out_size) {
    const float* feat = (const float*)d_in[0];
    const float* prot = (const float*)d_in[1];
    const float* ds   = (const float*)d_in[2];
    const float* temp = (const float*)d_in[3];
    float* out = (float*)d_out;

    cudaFuncSetAttribute(gemm_kernel, cudaFuncAttributeMaxDynamicSharedMemorySize, GEMM_SMEM);

    norm_features_kernel<<<B_ROWS, 256>>>(feat);
    norm_protos_kernel<<<C_PAD, 256>>>(prot);
    gemm_kernel<<<dim3(C_PAD / 128, B_ROWS / 128), 256, GEMM_SMEM>>>(ds, out);
    finalize_kernel<<<B_ROWS, 256>>>(out, temp);
}

// round 4
// speedup vs baseline: 2.0121x; 2.0121x over previous
#include <cuda_runtime.h>
#include <cuda_bf16.h>
#include <cstdint>

#define B_ROWS 16384
#define F_DIM  1024
#define C_COLS 1000
#define C_PAD  1024

// Scratch (static __device__ arrays allowed; no dynamic allocation)
__device__ __nv_bfloat16 g_Fb[(size_t)B_ROWS * F_DIM];   // normalized features, bf16
__device__ __nv_bfloat16 g_Pb[(size_t)C_PAD * F_DIM];    // normalized prototypes (padded), bf16
__device__ float g_rowsum[B_ROWS];

// ---------------------------------------------------------------------------
// Helpers (sm_80-era features only: cp.async, ldmatrix, mma.sync bf16 — the
// harness's ptxas target is plain sm_103, no 'a' features / tcgen05)
// ---------------------------------------------------------------------------
__device__ __forceinline__ uint32_t smem_u32(const void* p) {
    uint32_t a;
    asm("{ .reg .u64 t; cvta.to.shared.u64 t, %1; cvt.u32.u64 %0, t; }" : "=r"(a) : "l"(p));
    return a;
}
__device__ __forceinline__ void cp_async16(uint32_t dst, const void* src) {
    asm volatile("cp.async.cg.shared.global [%0], [%1], 16;" :: "r"(dst), "l"(src));
}
__device__ __forceinline__ void cp_commit() { asm volatile("cp.async.commit_group;" ::: "memory"); }

__device__ __forceinline__ void ldsm_x4(uint32_t& r0, uint32_t& r1, uint32_t& r2, uint32_t& r3,
                                        uint32_t addr) {
    asm volatile("ldmatrix.sync.aligned.m8n8.x4.shared.b16 {%0,%1,%2,%3}, [%4];"
                 : "=r"(r0), "=r"(r1), "=r"(r2), "=r"(r3) : "r"(addr));
}
__device__ __forceinline__ void mma_bf16(float* c, uint32_t a0, uint32_t a1, uint32_t a2,
                                         uint32_t a3, uint32_t b0, uint32_t b1) {
    asm volatile(
        "mma.sync.aligned.m16n8k16.row.col.f32.bf16.bf16.f32 "
        "{%0,%1,%2,%3}, {%4,%5,%6,%7}, {%8,%9}, {%0,%1,%2,%3};"
        : "+f"(c[0]), "+f"(c[1]), "+f"(c[2]), "+f"(c[3])
        : "r"(a0), "r"(a1), "r"(a2), "r"(a3), "r"(b0), "r"(b1));
}

// ---------------------------------------------------------------------------
// Kernels 1/2: L2-normalize rows -> bf16
// ---------------------------------------------------------------------------
__global__ void __launch_bounds__(256) norm_features_kernel(const float* __restrict__ in) {
    int row = blockIdx.x, tid = threadIdx.x;
    const float4* rin = (const float4*)(in + (size_t)row * F_DIM);
    float4 v = rin[tid];
    float ss = v.x * v.x + v.y * v.y + v.z * v.z + v.w * v.w;
#pragma unroll
    for (int o = 16; o; o >>= 1) ss += __shfl_xor_sync(0xffffffffu, ss, o);
    __shared__ float red[8];
    if ((tid & 31) == 0) red[tid >> 5] = ss;
    __syncthreads();
    if (tid < 8) {
        float t = red[tid];
#pragma unroll
        for (int o = 4; o; o >>= 1) t += __shfl_xor_sync(0x000000ffu, t, o);
        if (tid == 0) red[0] = t;
    }
    __syncthreads();
    float sc = 1.0f / fmaxf(sqrtf(red[0]), 1e-12f);
    __nv_bfloat162* dst = (__nv_bfloat162*)(g_Fb + (size_t)row * F_DIM);
    dst[tid * 2 + 0] = __floats2bfloat162_rn(v.x * sc, v.y * sc);
    dst[tid * 2 + 1] = __floats2bfloat162_rn(v.z * sc, v.w * sc);
    if (tid == 0) g_rowsum[row] = 0.0f;
}

__global__ void __launch_bounds__(256) norm_protos_kernel(const float* __restrict__ in) {
    int row = blockIdx.x, tid = threadIdx.x;
    __nv_bfloat162* dst = (__nv_bfloat162*)(g_Pb + (size_t)row * F_DIM);
    if (row >= C_COLS) {
        __nv_bfloat162 z = __floats2bfloat162_rn(0.f, 0.f);
        dst[tid * 2 + 0] = z;
        dst[tid * 2 + 1] = z;
        return;
    }
    const float4* rin = (const float4*)(in + (size_t)row * F_DIM);
    float4 v = rin[tid];
    float ss = v.x * v.x + v.y * v.y + v.z * v.z + v.w * v.w;
#pragma unroll
    for (int o = 16; o; o >>= 1) ss += __shfl_xor_sync(0xffffffffu, ss, o);
    __shared__ float red[8];
    if ((tid & 31) == 0) red[tid >> 5] = ss;
    __syncthreads();
    if (tid < 8) {
        float t = red[tid];
#pragma unroll
        for (int o = 4; o; o >>= 1) t += __shfl_xor_sync(0x000000ffu, t, o);
        if (tid == 0) red[0] = t;
    }
    __syncthreads();
    float sc = 1.0f / fmaxf(sqrtf(red[0]), 1e-12f);
    dst[tid * 2 + 0] = __floats2bfloat162_rn(v.x * sc, v.y * sc);
    dst[tid * 2 + 1] = __floats2bfloat162_rn(v.z * sc, v.w * sc);
}

// ---------------------------------------------------------------------------
// Kernel 3: bf16 mma.sync GEMM, CTA 128x128, BK=64, 2-stage cp.async pipeline
// 72KB smem -> 2 CTAs/SM (16 warps/SM) to test the occupancy hypothesis.
// 8 warps: wm = wid>>2 (0..1, 64 rows each), wn = wid&3 (0..3, 32 cols each)
// Epilogue: iso = |ds| * sqrt(max(1 - sim, 0)); direct store + row-sum atomics
// ---------------------------------------------------------------------------
#define STAGES 2
#define BK 64
#define KCHUNKS (F_DIM / BK)          // 16
#define PAD_BYTES 144                 // (64+8) bf16 per row
#define A_ST_BYTES (128 * PAD_BYTES)  // 18432
#define STAGE_BYTES (2 * A_ST_BYTES)  // 36864 (A then B)
#define GEMM_SMEM (STAGES * STAGE_BYTES)   // 73728

__device__ __forceinline__ void load_tile(uint32_t base, int kc, int m0, int n0, int tid) {
    const char* fb = (const char*)g_Fb;
    const char* pb = (const char*)g_Pb;
    uint32_t st = base + (uint32_t)(kc & (STAGES - 1)) * STAGE_BYTES;
#pragma unroll
    for (int it = 0; it < 4; it++) {
        int s = tid + it * 256;            // 0..1023
        int r = s >> 3, q = s & 7;
        cp_async16(st + (uint32_t)(r * PAD_BYTES + q * 16),
                   fb + (size_t)(m0 + r) * 2048 + (size_t)kc * 128 + q * 16);
    }
    uint32_t stB = st + A_ST_BYTES;
#pragma unroll
    for (int it = 0; it < 4; it++) {
        int s = tid + it * 256;
        int r = s >> 3, q = s & 7;
        cp_async16(stB + (uint32_t)(r * PAD_BYTES + q * 16),
                   pb + (size_t)(n0 + r) * 2048 + (size_t)kc * 128 + q * 16);
    }
    cp_commit();
}

__global__ void __launch_bounds__(256, 2) gemm_kernel(const float* __restrict__ ds,
                                                      float* __restrict__ out) {
    extern __shared__ char smem_raw[];
    uint32_t base = smem_u32(smem_raw);

    int tid = threadIdx.x;
    int wid = tid >> 5, l = tid & 31;
    int wm = wid >> 2, wn = wid & 3;
    int m0 = blockIdx.y * 128, n0 = blockIdx.x * 128;

    float c[4][4][4];
#pragma unroll
    for (int i = 0; i < 4; i++)
#pragma unroll
        for (int j = 0; j < 4; j++)
#pragma unroll
            for (int k = 0; k < 4; k++) c[i][j][k] = 0.0f;

    // prologue: prefetch chunk 0
    load_tile(base, 0, m0, n0, tid);

    for (int kc = 0; kc < KCHUNKS; kc++) {
        asm volatile("cp.async.wait_group 0;" ::: "memory");
        __syncthreads();

        int j = kc + 1;
        if (j < KCHUNKS) load_tile(base, j, m0, n0, tid);

        uint32_t st = base + (uint32_t)(kc & (STAGES - 1)) * STAGE_BYTES;
        uint32_t aBase = st + (uint32_t)(wm * 64) * PAD_BYTES;
        uint32_t bBase = st + A_ST_BYTES + (uint32_t)(wn * 32) * PAD_BYTES;

        int g = l >> 3;          // 0..3
        int r8 = l & 7;
#pragma unroll
        for (int ks = 0; ks < 4; ks++) {
            uint32_t a[4][4];
#pragma unroll
            for (int mt = 0; mt < 4; mt++) {
                // lanes: g0 rows 0-7 k0 | g1 rows 8-15 k0 | g2 rows 0-7 k8 | g3 rows 8-15 k8
                uint32_t addr = aBase + (uint32_t)((mt * 16 + (g & 1) * 8 + r8) * PAD_BYTES
                                                  + ks * 32 + (g >> 1) * 16);
                ldsm_x4(a[mt][0], a[mt][1], a[mt][2], a[mt][3], addr);
            }
            uint32_t b[4][2];
#pragma unroll
            for (int pair = 0; pair < 2; pair++) {
                // matrices: [ntile 2p, k-lo] [ntile 2p, k-hi] [ntile 2p+1, k-lo] [ntile 2p+1, k-hi]
                int ntile = pair * 2 + (g >> 1);
                uint32_t addr = bBase + (uint32_t)((ntile * 8 + r8) * PAD_BYTES
                                                  + ks * 32 + (g & 1) * 16);
                ldsm_x4(b[pair * 2][0], b[pair * 2][1], b[pair * 2 + 1][0], b[pair * 2 + 1][1], addr);
            }
#pragma unroll
            for (int mt = 0; mt < 4; mt++)
#pragma unroll
                for (int nt = 0; nt < 4; nt++)
                    mma_bf16(c[mt][nt], a[mt][0], a[mt][1], a[mt][2], a[mt][3],
                             b[nt][0], b[nt][1]);
        }
        __syncthreads();
    }

    // ---------------- epilogue ----------------
    float dsa = fabsf(ds[0]);
    float rs[4][2];
#pragma unroll
    for (int mt = 0; mt < 4; mt++) { rs[mt][0] = 0.0f; rs[mt][1] = 0.0f; }

#pragma unroll
    for (int mt = 0; mt < 4; mt++) {
        int mrow = m0 + wm * 64 + mt * 16 + (l >> 2);
#pragma unroll
        for (int nt = 0; nt < 4; nt++) {
            int col = n0 + wn * 32 + nt * 8 + 2 * (l & 3);
            float i0 = dsa * sqrtf(fmaxf(1.0f - c[mt][nt][0], 0.0f));
            float i1 = dsa * sqrtf(fmaxf(1.0f - c[mt][nt][1], 0.0f));
            float i2 = dsa * sqrtf(fmaxf(1.0f - c[mt][nt][2], 0.0f));
            float i3 = dsa * sqrtf(fmaxf(1.0f - c[mt][nt][3], 0.0f));
            if (col < C_COLS) {             // col even, C_COLS even -> col+1 valid too
                rs[mt][0] += i0 + i1;
                rs[mt][1] += i2 + i3;
                float2 v01 = make_float2(i0, i1);
                float2 v23 = make_float2(i2, i3);
                *(float2*)(out + (size_t)mrow * C_COLS + col) = v01;
                *(float2*)(out + (size_t)(mrow + 8) * C_COLS + col) = v23;
            }
        }
    }
    // reduce row sums over the 4 lanes sharing a row (xor 1, 2), then atomics
#pragma unroll
    for (int mt = 0; mt < 4; mt++) {
#pragma unroll
        for (int h = 0; h < 2; h++) {
            float v = rs[mt][h];
            v += __shfl_xor_sync(0xffffffffu, v, 1);
            v += __shfl_xor_sync(0xffffffffu, v, 2);
            if ((l & 3) == 0) {
                int mrow = m0 + wm * 64 + mt * 16 + (l >> 2) + h * 8;
                atomicAdd(&g_rowsum[mrow], v);
            }
        }
    }
}

// ---------------------------------------------------------------------------
// Kernel 4: logits = -(iso + rowmean) / temperature, flat float4 grid.
// 16384 rows x 250 float4/row; row = idx/250 (compiler mul-shift).
// ---------------------------------------------------------------------------
#define F4_PER_ROW (C_COLS / 4)              // 250
#define FIN_TOTAL  (B_ROWS * F4_PER_ROW)     // 4,096,000

__global__ void __launch_bounds__(256) finalize_kernel(float* __restrict__ out,
                                                       const float* __restrict__ temp) {
    unsigned v = blockIdx.x * 256u + threadIdx.x;
    if (v >= (unsigned)FIN_TOTAL) return;
    unsigned row = v / (unsigned)F4_PER_ROW;
    float m = __ldg(&g_rowsum[row]) * (1.0f / (float)C_COLS);
    float invt = 1.0f / __ldg(temp);
    float4 x = *(float4*)(out + (size_t)v * 4);
    x.x = -(x.x + m) * invt;
    x.y = -(x.y + m) * invt;
    x.z = -(x.z + m) * invt;
    x.w = -(x.w + m) * invt;
    *(float4*)(out + (size_t)v * 4) = x;
}

// ---------------------------------------------------------------------------
extern "C" void kernel_launch(void* const* d_in, const int* in_sizes, int n_in,
                              void* d_out, int out_size) {
    const float* feat = (const float*)d_in[0];
    const float* prot = (const float*)d_in[1];
    const float* ds   = (const float*)d_in[2];
    const float* temp = (const float*)d_in[3];
    float* out = (float*)d_out;

    cudaFuncSetAttribute(gemm_kernel, cudaFuncAttributeMaxDynamicSharedMemorySize, GEMM_SMEM);

    norm_features_kernel<<<B_ROWS, 256>>>(feat);
    norm_protos_kernel<<<C_PAD, 256>>>(prot);
    gemm_kernel<<<dim3(C_PAD / 128, B_ROWS / 128), 256, GEMM_SMEM>>>(ds, out);
    finalize_kernel<<<(FIN_TOTAL + 255) / 256, 256>>>(out, temp);
}